// round 3
// baseline (speedup 1.0000x reference)
#include <cuda_runtime.h>
#include <cuda_bf16.h>

// Problem constants (fixed by the reference)
#define BATCH      512
#define SEQ        200
#define EMB        256
#define NUM_SKILLS 300
#define D3         21   // CURVE_DIM//3
#define DM         22   // D3 + CURVE_DIM%3

// Precomputed affine basis vectors: traj[b,t,e] = qf*A[e] + att*B[e] + mast*C[e] + D[e]
__device__ __align__(16) float g_A[EMB];
__device__ __align__(16) float g_B[EMB];
__device__ __align__(16) float g_C[EMB];
__device__ __align__(16) float g_D[EMB];

// One block, 256 threads: each thread e folds proj_w row e against the tiny
// Linear(1,d) weights. proj_w is [EMB, 64] row-major.
__global__ void te_precompute(const float* __restrict__ skill_w,
                              const float* __restrict__ skill_b,
                              const float* __restrict__ att_w,
                              const float* __restrict__ att_b,
                              const float* __restrict__ mast_w,
                              const float* __restrict__ mast_b,
                              const float* __restrict__ proj_w,
                              const float* __restrict__ proj_b) {
    int e = threadIdx.x;
    if (e >= EMB) return;
    const float* row = proj_w + e * 64;
    float a = 0.f, b = 0.f, c = 0.f, d = proj_b[e];
#pragma unroll
    for (int i = 0; i < D3; i++) {
        float w = row[i];
        a = fmaf(skill_w[i], w, a);
        d = fmaf(skill_b[i], w, d);
    }
#pragma unroll
    for (int i = 0; i < D3; i++) {
        float w = row[D3 + i];
        b = fmaf(att_w[i], w, b);
        d = fmaf(att_b[i], w, d);
    }
#pragma unroll
    for (int i = 0; i < DM; i++) {
        float w = row[2 * D3 + i];
        c = fmaf(mast_w[i], w, c);
        d = fmaf(mast_b[i], w, d);
    }
    g_A[e] = a; g_B[e] = b; g_C[e] = c; g_D[e] = d;
}

// One block per batch row, 256 threads.
__global__ __launch_bounds__(256) void te_main(const int* __restrict__ q,
                                               const int* __restrict__ r,
                                               float* __restrict__ out) {
    __shared__ int   sq[SEQ];
    __shared__ int   sr[SEQ];
    __shared__ float s_qf[SEQ];
    __shared__ float s_att[SEQ];
    __shared__ float s_mast[SEQ];
    __shared__ float s_valid[SEQ];

    const int b   = blockIdx.x;
    const int tid = threadIdx.x;

    if (tid < SEQ) {
        sq[tid] = q[b * SEQ + tid];
        sr[tid] = r[b * SEQ + tid];
    }
    __syncthreads();

    // Phase 1: running counts by direct counting (parallel over t).
    // attempts[t] = #{t' <= t : valid(t') && q[t']==q[t]}, correct similarly with r.
    if (tid < SEQ) {
        const int qt = sq[tid];
        int att = 0, cor = 0;
        for (int tp = 0; tp <= tid; tp++) {
            int qp = sq[tp];
            // valid(tp) && match — shared reads at index tp are warp-broadcast
            if ((unsigned)qp < NUM_SKILLS && qp == qt) {
                att += 1;
                cor += sr[tp];
            }
        }
        const bool valid = (unsigned)qt < NUM_SKILLS;
        const float af = (float)att;
        s_qf[tid]    = (float)qt;
        s_att[tid]   = af;
        s_mast[tid]  = (float)cor / fmaxf(af, 1.0f);
        s_valid[tid] = valid ? 1.0f : 0.0f;
    }
    __syncthreads();

    // Phase 2: stream output rows. 4 t-subgroups x 64 lanes; each lane owns a
    // float4 slice of the 256-wide embedding -> 1KB fully-coalesced stores.
    const int lane = tid & 63;   // float4 index within the row
    const int tg   = tid >> 6;   // 0..3: which t this subgroup handles

    const float4 A = reinterpret_cast<const float4*>(g_A)[lane];
    const float4 Bv = reinterpret_cast<const float4*>(g_B)[lane];
    const float4 C = reinterpret_cast<const float4*>(g_C)[lane];
    const float4 D = reinterpret_cast<const float4*>(g_D)[lane];

    float4* __restrict__ out4 = reinterpret_cast<float4*>(out);

#pragma unroll 2
    for (int t = tg; t < SEQ; t += 4) {
        const float qf = s_qf[t];
        const float at = s_att[t];
        const float ms = s_mast[t];
        const float v  = s_valid[t];
        float4 o;
        o.x = v * fmaf(qf, A.x, fmaf(at, Bv.x, fmaf(ms, C.x, D.x)));
        o.y = v * fmaf(qf, A.y, fmaf(at, Bv.y, fmaf(ms, C.y, D.y)));
        o.z = v * fmaf(qf, A.z, fmaf(at, Bv.z, fmaf(ms, C.z, D.z)));
        o.w = v * fmaf(qf, A.w, fmaf(at, Bv.w, fmaf(ms, C.w, D.w)));
        // Write-once output: streaming store, skip L2 retention
        __stcs(&out4[(size_t)(b * SEQ + t) * (EMB / 4) + lane], o);
    }
}

extern "C" void kernel_launch(void* const* d_in, const int* in_sizes, int n_in,
                              void* d_out, int out_size) {
    // metadata order: q, r, qry, skill_w, skill_b, att_w, att_b,
    //                 mast_w, mast_b, proj_w, proj_b
    const int*   q       = (const int*)d_in[0];
    const int*   r       = (const int*)d_in[1];
    // d_in[2] = qry — unused by the reference
    const float* skill_w = (const float*)d_in[3];
    const float* skill_b = (const float*)d_in[4];
    const float* att_w   = (const float*)d_in[5];
    const float* att_b   = (const float*)d_in[6];
    const float* mast_w  = (const float*)d_in[7];
    const float* mast_b  = (const float*)d_in[8];
    const float* proj_w  = (const float*)d_in[9];
    const float* proj_b  = (const float*)d_in[10];
    float* out = (float*)d_out;

    te_precompute<<<1, 256>>>(skill_w, skill_b, att_w, att_b,
                              mast_w, mast_b, proj_w, proj_b);
    te_main<<<BATCH, 256>>>(q, r, out);
}